// round 1
// baseline (speedup 1.0000x reference)
#include <cuda_runtime.h>
#include <cuda_bf16.h>
#include <cstdint>

#define BSZ      2
#define SEQ      2048
#define DIM      2048
#define N_HEADS  32
#define N_KVH    8
#define HD       64
#define N_REP    4
#define ROWS     (BSZ*SEQ)          // 4096
#define KVDIM    (N_KVH*HD)         // 512

// ---------------- scratch (device globals; no allocations allowed) ----------
__device__ __align__(256) float g_Q[ROWS * DIM];     // 32 MB
__device__ __align__(256) float g_K[ROWS * KVDIM];   // 8 MB
__device__ __align__(256) float g_V[ROWS * KVDIM];   // 8 MB
__device__ __align__(256) float g_A[ROWS * DIM];     // 32 MB

// ---------------- fp32 SGEMM: C[M,N] = A[M,K] @ B[K,N] ----------------------
// 128x128 tile, BK=16, 256 threads, 8x8 per thread. M,N,K multiples of tile.
__global__ __launch_bounds__(256) void sgemm128(const float* __restrict__ A,
                                                const float* __restrict__ B,
                                                float* __restrict__ C,
                                                int M, int N, int K) {
    __shared__ float As[16][128];
    __shared__ float Bs[16][128];

    const int tid = threadIdx.x;
    const int bx = blockIdx.x;   // N tile
    const int by = blockIdx.y;   // M tile
    const int tx = tid & 15;
    const int ty = tid >> 4;

    const float* Aptr = A + (size_t)by * 128 * K;
    const float* Bptr = B + (size_t)bx * 128;

    const int arow  = tid >> 2;         // 0..63  (+64 second pass)
    const int acol4 = (tid & 3) << 2;   // 0,4,8,12
    const int brow  = tid >> 5;         // 0..7   (+8 second pass)
    const int bcol4 = (tid & 31) << 2;  // 0..124

    float acc[8][8];
    #pragma unroll
    for (int i = 0; i < 8; i++)
        #pragma unroll
        for (int j = 0; j < 8; j++) acc[i][j] = 0.f;

    for (int k0 = 0; k0 < K; k0 += 16) {
        #pragma unroll
        for (int i = 0; i < 2; i++) {
            int r = arow + i * 64;
            float4 v = *(const float4*)(Aptr + (size_t)r * K + k0 + acol4);
            As[acol4 + 0][r] = v.x;
            As[acol4 + 1][r] = v.y;
            As[acol4 + 2][r] = v.z;
            As[acol4 + 3][r] = v.w;
        }
        #pragma unroll
        for (int i = 0; i < 2; i++) {
            int r = brow + i * 8;
            *(float4*)(&Bs[r][bcol4]) =
                *(const float4*)(Bptr + (size_t)(k0 + r) * N + bcol4);
        }
        __syncthreads();

        #pragma unroll
        for (int k = 0; k < 16; k++) {
            float ra[8], rb[8];
            float4 a0 = *(const float4*)(&As[k][ty * 8]);
            float4 a1 = *(const float4*)(&As[k][ty * 8 + 4]);
            ra[0]=a0.x; ra[1]=a0.y; ra[2]=a0.z; ra[3]=a0.w;
            ra[4]=a1.x; ra[5]=a1.y; ra[6]=a1.z; ra[7]=a1.w;
            float4 b0 = *(const float4*)(&Bs[k][tx * 8]);
            float4 b1 = *(const float4*)(&Bs[k][tx * 8 + 4]);
            rb[0]=b0.x; rb[1]=b0.y; rb[2]=b0.z; rb[3]=b0.w;
            rb[4]=b1.x; rb[5]=b1.y; rb[6]=b1.z; rb[7]=b1.w;
            #pragma unroll
            for (int i = 0; i < 8; i++)
                #pragma unroll
                for (int j = 0; j < 8; j++)
                    acc[i][j] += ra[i] * rb[j];
        }
        __syncthreads();
    }

    float* Cp = C + (size_t)(by * 128 + ty * 8) * N + bx * 128 + tx * 8;
    #pragma unroll
    for (int i = 0; i < 8; i++) {
        float4 c0 = make_float4(acc[i][0], acc[i][1], acc[i][2], acc[i][3]);
        float4 c1 = make_float4(acc[i][4], acc[i][5], acc[i][6], acc[i][7]);
        *(float4*)(Cp + (size_t)i * N)     = c0;
        *(float4*)(Cp + (size_t)i * N + 4) = c1;
    }
}

// ---------------- RoPE (in place) -------------------------------------------
__global__ void rope_kernel(float* __restrict__ t,
                            const float* __restrict__ cs,
                            const float* __restrict__ sn,
                            int n_heads, int total) {
    int idx = blockIdx.x * blockDim.x + threadIdx.x;
    if (idx >= total) return;
    int p = idx & 31;                     // pair index 0..31
    int h = (idx >> 5) % n_heads;
    int row = idx / (32 * n_heads);       // 0..ROWS-1
    int s = row & (SEQ - 1);
    float c = cs[s * 32 + p];
    float si = sn[s * 32 + p];
    size_t base = (size_t)row * (n_heads * HD) + h * HD + p * 2;
    float tr = t[base], ti = t[base + 1];
    t[base]     = tr * c - ti * si;
    t[base + 1] = tr * si + ti * c;
}

// ---------------- causal flash attention (fp32) -----------------------------
// grid (32 q-tiles, 32 heads, 2 batch); 256 threads = 64 rows x 4 col groups
#define ST 68   // padded smem stride (bank-conflict free, float4 aligned)

__global__ __launch_bounds__(256) void attn_kernel(float* __restrict__ Aout) {
    extern __shared__ float sm[];
    float* Qs = sm;                // [64][ST]
    float* Kt = sm + 64 * ST;      // [d][c] transposed
    float* Vs = sm + 2 * 64 * ST;  // [k][c]
    float* Ps = sm + 3 * 64 * ST;  // [r][k]

    const int qt = blockIdx.x, h = blockIdx.y, b = blockIdx.z;
    const int kvh = h >> 2;     // N_REP = 4
    const int tid = threadIdx.x;
    const int r = tid >> 2;     // row in tile 0..63
    const int g = tid & 3;      // col group: cols [16g, 16g+16)

    // load Q tile
    const float* Qg = g_Q + ((size_t)(b * SEQ + qt * 64)) * DIM + h * HD;
    for (int i = tid; i < 64 * 16; i += 256) {
        int row = i >> 4, c4 = (i & 15) << 2;
        *(float4*)&Qs[row * ST + c4] = *(const float4*)(Qg + (size_t)row * DIM + c4);
    }

    float m = -1e30f, l = 0.f;
    float o[16];
    #pragma unroll
    for (int j = 0; j < 16; j++) o[j] = 0.f;
    const float scale = 0.125f;  // 1/sqrt(64)

    for (int kb = 0; kb <= qt; kb++) {
        __syncthreads();
        const float* Kg = g_K + ((size_t)(b * SEQ + kb * 64)) * KVDIM + kvh * HD;
        const float* Vg = g_V + ((size_t)(b * SEQ + kb * 64)) * KVDIM + kvh * HD;
        for (int i = tid; i < 64 * 16; i += 256) {
            int row = i >> 4, c4 = (i & 15) << 2;
            float4 kv = *(const float4*)(Kg + (size_t)row * KVDIM + c4);
            Kt[(c4 + 0) * ST + row] = kv.x;
            Kt[(c4 + 1) * ST + row] = kv.y;
            Kt[(c4 + 2) * ST + row] = kv.z;
            Kt[(c4 + 3) * ST + row] = kv.w;
            *(float4*)&Vs[row * ST + c4] = *(const float4*)(Vg + (size_t)row * KVDIM + c4);
        }
        __syncthreads();

        // S = Q K^T  (each thread: 16 cols of its row)
        float acc[16];
        #pragma unroll
        for (int j = 0; j < 16; j++) acc[j] = 0.f;
        #pragma unroll
        for (int d4 = 0; d4 < 64; d4 += 4) {
            float4 q = *(const float4*)&Qs[r * ST + d4];
            float qv[4] = {q.x, q.y, q.z, q.w};
            #pragma unroll
            for (int dd = 0; dd < 4; dd++) {
                const float* kt = &Kt[(d4 + dd) * ST + g * 16];
                float4 k0 = *(const float4*)(kt);
                float4 k1 = *(const float4*)(kt + 4);
                float4 k2 = *(const float4*)(kt + 8);
                float4 k3 = *(const float4*)(kt + 12);
                float qd = qv[dd];
                acc[0]  += qd * k0.x; acc[1]  += qd * k0.y;
                acc[2]  += qd * k0.z; acc[3]  += qd * k0.w;
                acc[4]  += qd * k1.x; acc[5]  += qd * k1.y;
                acc[6]  += qd * k1.z; acc[7]  += qd * k1.w;
                acc[8]  += qd * k2.x; acc[9]  += qd * k2.y;
                acc[10] += qd * k2.z; acc[11] += qd * k2.w;
                acc[12] += qd * k3.x; acc[13] += qd * k3.y;
                acc[14] += qd * k3.z; acc[15] += qd * k3.w;
            }
        }
        #pragma unroll
        for (int j = 0; j < 16; j++) acc[j] *= scale;
        if (kb == qt) {
            #pragma unroll
            for (int j = 0; j < 16; j++)
                if (g * 16 + j > r) acc[j] = -1e30f;
        }

        // online softmax (row reduction across the 4 threads of each row)
        float mx = acc[0];
        #pragma unroll
        for (int j = 1; j < 16; j++) mx = fmaxf(mx, acc[j]);
        mx = fmaxf(mx, __shfl_xor_sync(0xffffffffu, mx, 1));
        mx = fmaxf(mx, __shfl_xor_sync(0xffffffffu, mx, 2));
        float mnew = fmaxf(m, mx);
        float alpha = __expf(m - mnew);
        float ls = 0.f;
        #pragma unroll
        for (int j = 0; j < 16; j++) {
            float p = __expf(acc[j] - mnew);
            acc[j] = p;
            ls += p;
        }
        ls += __shfl_xor_sync(0xffffffffu, ls, 1);
        ls += __shfl_xor_sync(0xffffffffu, ls, 2);
        l = l * alpha + ls;
        m = mnew;
        #pragma unroll
        for (int j = 0; j < 16; j++) o[j] *= alpha;

        // write P to smem
        *(float4*)&Ps[r * ST + g * 16]      = make_float4(acc[0], acc[1], acc[2], acc[3]);
        *(float4*)&Ps[r * ST + g * 16 + 4]  = make_float4(acc[4], acc[5], acc[6], acc[7]);
        *(float4*)&Ps[r * ST + g * 16 + 8]  = make_float4(acc[8], acc[9], acc[10], acc[11]);
        *(float4*)&Ps[r * ST + g * 16 + 12] = make_float4(acc[12], acc[13], acc[14], acc[15]);
        __syncthreads();

        // O += P @ V
        #pragma unroll 8
        for (int kk = 0; kk < 64; kk++) {
            float p = Ps[r * ST + kk];
            const float* vp = &Vs[kk * ST + g * 16];
            float4 v0 = *(const float4*)(vp);
            float4 v1 = *(const float4*)(vp + 4);
            float4 v2 = *(const float4*)(vp + 8);
            float4 v3 = *(const float4*)(vp + 12);
            o[0]  += p * v0.x; o[1]  += p * v0.y; o[2]  += p * v0.z; o[3]  += p * v0.w;
            o[4]  += p * v1.x; o[5]  += p * v1.y; o[6]  += p * v1.z; o[7]  += p * v1.w;
            o[8]  += p * v2.x; o[9]  += p * v2.y; o[10] += p * v2.z; o[11] += p * v2.w;
            o[12] += p * v3.x; o[13] += p * v3.y; o[14] += p * v3.z; o[15] += p * v3.w;
        }
    }

    float inv = 1.f / l;
    float* Ag = g_A + ((size_t)(b * SEQ + qt * 64 + r)) * DIM + h * HD + g * 16;
    *(float4*)(Ag)      = make_float4(o[0]*inv,  o[1]*inv,  o[2]*inv,  o[3]*inv);
    *(float4*)(Ag + 4)  = make_float4(o[4]*inv,  o[5]*inv,  o[6]*inv,  o[7]*inv);
    *(float4*)(Ag + 8)  = make_float4(o[8]*inv,  o[9]*inv,  o[10]*inv, o[11]*inv);
    *(float4*)(Ag + 12) = make_float4(o[12]*inv, o[13]*inv, o[14]*inv, o[15]*inv);
}

// ---------------- launch ----------------------------------------------------
extern "C" void kernel_launch(void* const* d_in, const int* in_sizes, int n_in,
                              void* d_out, int out_size) {
    const float* x  = (const float*)d_in[0];
    const float* fc = (const float*)d_in[1];
    const float* fs = (const float*)d_in[2];
    const float* wq = (const float*)d_in[3];
    const float* wk = (const float*)d_in[4];
    const float* wv = (const float*)d_in[5];
    const float* wo = (const float*)d_in[6];
    float* out = (float*)d_out;

    void *pQ, *pK, *pV, *pA;
    cudaGetSymbolAddress(&pQ, g_Q);
    cudaGetSymbolAddress(&pK, g_K);
    cudaGetSymbolAddress(&pV, g_V);
    cudaGetSymbolAddress(&pA, g_A);
    float* Q = (float*)pQ;
    float* K = (float*)pK;
    float* V = (float*)pV;
    float* A = (float*)pA;

    // projections
    sgemm128<<<dim3(DIM / 128, ROWS / 128), 256>>>(x, wq, Q, ROWS, DIM, DIM);
    sgemm128<<<dim3(KVDIM / 128, ROWS / 128), 256>>>(x, wk, K, ROWS, KVDIM, DIM);
    sgemm128<<<dim3(KVDIM / 128, ROWS / 128), 256>>>(x, wv, V, ROWS, KVDIM, DIM);

    // RoPE
    {
        int totq = ROWS * N_HEADS * 32;
        rope_kernel<<<(totq + 255) / 256, 256>>>(Q, fc, fs, N_HEADS, totq);
        int totk = ROWS * N_KVH * 32;
        rope_kernel<<<(totk + 255) / 256, 256>>>(K, fc, fs, N_KVH, totk);
    }

    // attention
    {
        size_t smem = 4 * 64 * ST * sizeof(float);  // ~69.6 KB
        cudaFuncSetAttribute(attn_kernel,
                             cudaFuncAttributeMaxDynamicSharedMemorySize,
                             (int)smem);
        attn_kernel<<<dim3(SEQ / 64, N_HEADS, BSZ), 256, smem>>>(A);
    }

    // output projection
    sgemm128<<<dim3(DIM / 128, ROWS / 128), 256>>>(A, wo, out, ROWS, DIM, DIM);
}

// round 2
// speedup vs baseline: 3.5135x; 3.5135x over previous
#include <cuda_runtime.h>
#include <cuda_bf16.h>
#include <cstdint>

#define BSZ      2
#define SEQ      2048
#define DIM      2048
#define N_HEADS  32
#define N_KVH    8
#define HD       64
#define N_REP    4
#define ROWS     (BSZ*SEQ)          // 4096
#define KVDIM    (N_KVH*HD)         // 512

// ---------------- scratch (device globals; no allocations allowed) ----------
__device__ __align__(256) float g_Q[ROWS * DIM];     // 32 MB
__device__ __align__(256) float g_K[ROWS * KVDIM];   // 8 MB
__device__ __align__(256) float g_V[ROWS * KVDIM];   // 8 MB
__device__ __align__(256) float g_A[ROWS * DIM];     // 32 MB

// ---------------- helpers ----------------------------------------------------
// Split fp32 pair into (hi, lo) packed bf16x2. Low 16 bits = first (even-k) elem.
__device__ __forceinline__ void split_pack(float x, float y, uint32_t& hv, uint32_t& lv) {
    __nv_bfloat162 hb = __floats2bfloat162_rn(x, y);   // .x = x (low half)
    hv = *reinterpret_cast<uint32_t*>(&hb);
    float rx = x - __bfloat162float(hb.x);
    float ry = y - __bfloat162float(hb.y);
    __nv_bfloat162 lb = __floats2bfloat162_rn(rx, ry);
    lv = *reinterpret_cast<uint32_t*>(&lb);
}

__device__ __forceinline__ void mma_bf16(float* c,
        uint32_t a0, uint32_t a1, uint32_t a2, uint32_t a3,
        uint32_t b0, uint32_t b1) {
    asm volatile(
        "mma.sync.aligned.m16n8k16.row.col.f32.bf16.bf16.f32 "
        "{%0,%1,%2,%3}, {%4,%5,%6,%7}, {%8,%9}, {%0,%1,%2,%3};"
        : "+f"(c[0]), "+f"(c[1]), "+f"(c[2]), "+f"(c[3])
        : "r"(a0), "r"(a1), "r"(a2), "r"(a3), "r"(b0), "r"(b1));
}

// ---------------- split-bf16 tensor-core GEMM: C[M,N] = A[M,K] @ B[K,N] ------
// 128x128 tile, BK=32, 256 threads (8 warps, 64x32 warp tiles).
#define SAg 20   // u32 stride for A smem (16 pairs + 4 pad): bank=4m+p, conflict-free
#define SBg 20

__global__ __launch_bounds__(256) void gemm_split(const float* __restrict__ A,
                                                  const float* __restrict__ B,
                                                  float* __restrict__ C,
                                                  int M, int N, int K) {
    __shared__ uint32_t AH[128 * SAg], AL[128 * SAg];
    __shared__ uint32_t BH[128 * SBg], BL[128 * SBg];

    const int tid = threadIdx.x;
    const int warp = tid >> 5, lane = tid & 31;
    const int tg = lane >> 2, t4 = lane & 3;      // groupID, tid-in-group
    const int wm = (warp >> 2) * 64;              // warp row  (0/64)
    const int wn = (warp & 3) * 32;               // warp col  (0/32/64/96)

    const float* Ap = A + (size_t)blockIdx.y * 128 * K;
    const float* Bp = B + blockIdx.x * 128;

    float acc[4][4][4];
    #pragma unroll
    for (int i = 0; i < 4; i++)
        #pragma unroll
        for (int j = 0; j < 4; j++)
            #pragma unroll
            for (int c = 0; c < 4; c++) acc[i][j][c] = 0.f;

    const int ar = tid >> 1;            // A row this thread fills
    const int akh = (tid & 1) * 16;     // k offset (0 / 16)

    for (int k0 = 0; k0 < K; k0 += 32) {
        // ---- stage A chunk (128 x 32) as split-bf16 pairs ----
        {
            float f[16];
            const float* src = Ap + (size_t)ar * K + k0 + akh;
            *(float4*)(f)      = *(const float4*)(src);
            *(float4*)(f + 4)  = *(const float4*)(src + 4);
            *(float4*)(f + 8)  = *(const float4*)(src + 8);
            *(float4*)(f + 12) = *(const float4*)(src + 12);
            int base = ar * SAg + (akh >> 1);
            #pragma unroll
            for (int i = 0; i < 8; i++) {
                uint32_t h, l;
                split_pack(f[2 * i], f[2 * i + 1], h, l);
                AH[base + i] = h; AL[base + i] = l;
            }
        }
        // ---- stage B chunk (32 x 128), transposed-packed: BH[n][kpair] ----
        #pragma unroll
        for (int jj = 0; jj < 8; jj++) {
            int id = tid + 256 * jj;
            int p = id >> 7, n = id & 127;
            float x = Bp[(size_t)(k0 + 2 * p) * N + n];
            float y = Bp[(size_t)(k0 + 2 * p + 1) * N + n];
            uint32_t h, l;
            split_pack(x, y, h, l);
            BH[n * SBg + p] = h; BL[n * SBg + p] = l;
        }
        __syncthreads();

        #pragma unroll
        for (int s = 0; s < 2; s++) {       // two k16 steps per chunk
            uint32_t aH[4][4], aL[4][4];
            #pragma unroll
            for (int i = 0; i < 4; i++) {
                int m0 = wm + 16 * i;
                int ba = (m0 + tg) * SAg + 8 * s + t4;
                int bb = (m0 + 8 + tg) * SAg + 8 * s + t4;
                aH[i][0] = AH[ba]; aH[i][1] = AH[bb];
                aH[i][2] = AH[ba + 4]; aH[i][3] = AH[bb + 4];
                aL[i][0] = AL[ba]; aL[i][1] = AL[bb];
                aL[i][2] = AL[ba + 4]; aL[i][3] = AL[bb + 4];
            }
            #pragma unroll
            for (int j = 0; j < 4; j++) {
                int nb = (wn + 8 * j + tg) * SBg + 8 * s + t4;
                uint32_t bH0 = BH[nb], bH1 = BH[nb + 4];
                uint32_t bL0 = BL[nb], bL1 = BL[nb + 4];
                #pragma unroll
                for (int i = 0; i < 4; i++) {
                    mma_bf16(acc[i][j], aH[i][0], aH[i][1], aH[i][2], aH[i][3], bH0, bH1);
                    mma_bf16(acc[i][j], aH[i][0], aH[i][1], aH[i][2], aH[i][3], bL0, bL1);
                    mma_bf16(acc[i][j], aL[i][0], aL[i][1], aL[i][2], aL[i][3], bH0, bH1);
                }
            }
        }
        __syncthreads();
    }

    // ---- epilogue ----
    #pragma unroll
    for (int i = 0; i < 4; i++) {
        int r0 = blockIdx.y * 128 + wm + 16 * i + tg;
        #pragma unroll
        for (int j = 0; j < 4; j++) {
            int col = blockIdx.x * 128 + wn + 8 * j + 2 * t4;
            *(float2*)(C + (size_t)r0 * N + col) = make_float2(acc[i][j][0], acc[i][j][1]);
            *(float2*)(C + (size_t)(r0 + 8) * N + col) = make_float2(acc[i][j][2], acc[i][j][3]);
        }
    }
}

// ---------------- RoPE (in place) -------------------------------------------
__global__ void rope_kernel(float* __restrict__ t,
                            const float* __restrict__ cs,
                            const float* __restrict__ sn,
                            int n_heads, int total) {
    int idx = blockIdx.x * blockDim.x + threadIdx.x;
    if (idx >= total) return;
    int p = idx & 31;
    int h = (idx >> 5) % n_heads;
    int row = idx / (32 * n_heads);
    int s = row & (SEQ - 1);
    float c = cs[s * 32 + p];
    float si = sn[s * 32 + p];
    size_t base = (size_t)row * (n_heads * HD) + h * HD + p * 2;
    float tr = t[base], ti = t[base + 1];
    t[base]     = tr * c - ti * si;
    t[base + 1] = tr * si + ti * c;
}

// ---------------- causal flash attention (split-bf16 mma) -------------------
// CTA: 64 q-rows x one (b,h); 4 warps, each owns 16 q-rows. KV tile = 64.
#define SAT 36   // u32 stride (32 pairs + 4 pad): bank = 4*row + pair, conflict-free

__global__ __launch_bounds__(128) void attn_mma() {
    extern __shared__ uint32_t smu[];
    uint32_t* KH = smu;               // [64][SAT]  K as B-frag: [kv][dpair]
    uint32_t* KL = KH + 64 * SAT;
    uint32_t* VH = KL + 64 * SAT;     // V as B-frag: [d][kvpair]
    uint32_t* VL = VH + 64 * SAT;
    uint32_t* PH = VL + 64 * SAT;     // P as A-frag: [qrow][kvpair] (also Q staging)
    uint32_t* PL = PH + 64 * SAT;

    const int qt = blockIdx.x, h = blockIdx.y, b = blockIdx.z;
    const int kvh = h >> 2;
    const int tid = threadIdx.x;
    const int w = tid >> 5, lane = tid & 31;
    const int tg = lane >> 2, t4 = lane & 3;
    const int rA = w * 16 + tg, rB = rA + 8;   // this thread's two q-rows (local)

    // ---- stage Q tile, pull A-fragments into registers ----
    const float* Qg = g_Q + (size_t)(b * SEQ + qt * 64) * DIM + h * HD;
    #pragma unroll
    for (int jj = 0; jj < 16; jj++) {
        int id = tid + 128 * jj;
        int m = id >> 5, p = id & 31;
        float2 q2 = *(const float2*)(Qg + (size_t)m * DIM + 2 * p);
        uint32_t hh, ll;
        split_pack(q2.x, q2.y, hh, ll);
        PH[m * SAT + p] = hh; PL[m * SAT + p] = ll;
    }
    __syncthreads();
    uint32_t qH[4][4], qL[4][4];
    #pragma unroll
    for (int s = 0; s < 4; s++) {
        int ba = rA * SAT + 8 * s + t4, bb = rB * SAT + 8 * s + t4;
        qH[s][0] = PH[ba]; qH[s][1] = PH[bb]; qH[s][2] = PH[ba + 4]; qH[s][3] = PH[bb + 4];
        qL[s][0] = PL[ba]; qL[s][1] = PL[bb]; qL[s][2] = PL[ba + 4]; qL[s][3] = PL[bb + 4];
    }
    __syncthreads();

    float oacc[8][4];
    #pragma unroll
    for (int j = 0; j < 8; j++)
        #pragma unroll
        for (int c = 0; c < 4; c++) oacc[j][c] = 0.f;
    float mA = -1e30f, mB = -1e30f, lA = 0.f, lB = 0.f;
    const float scale = 0.125f;

    const float* Kg0 = g_K + (size_t)(b * SEQ) * KVDIM + kvh * HD;
    const float* Vg0 = g_V + (size_t)(b * SEQ) * KVDIM + kvh * HD;

    for (int kb = 0; kb <= qt; kb++) {
        const float* Kg = Kg0 + (size_t)kb * 64 * KVDIM;
        const float* Vg = Vg0 + (size_t)kb * 64 * KVDIM;
        // ---- stage K tile: KH[kv][dpair] ----
        #pragma unroll
        for (int jj = 0; jj < 16; jj++) {
            int id = tid + 128 * jj;
            int kv = id >> 5, p = id & 31;
            float2 k2 = *(const float2*)(Kg + (size_t)kv * KVDIM + 2 * p);
            uint32_t hh, ll;
            split_pack(k2.x, k2.y, hh, ll);
            KH[kv * SAT + p] = hh; KL[kv * SAT + p] = ll;
        }
        // ---- stage V tile transposed: VH[d][kvpair] ----
        #pragma unroll
        for (int jj = 0; jj < 16; jj++) {
            int id = tid + 128 * jj;
            int d = id & 63, p = id >> 6;
            float x = Vg[(size_t)(2 * p) * KVDIM + d];
            float y = Vg[(size_t)(2 * p + 1) * KVDIM + d];
            uint32_t hh, ll;
            split_pack(x, y, hh, ll);
            VH[d * SAT + p] = hh; VL[d * SAT + p] = ll;
        }
        __syncthreads();

        // ---- S = Q K^T (m16 x n64 per warp) ----
        float sacc[8][4];
        #pragma unroll
        for (int j = 0; j < 8; j++)
            #pragma unroll
            for (int c = 0; c < 4; c++) sacc[j][c] = 0.f;
        #pragma unroll
        for (int s = 0; s < 4; s++) {
            #pragma unroll
            for (int j = 0; j < 8; j++) {
                int nb = (8 * j + tg) * SAT + 8 * s + t4;
                uint32_t bH0 = KH[nb], bH1 = KH[nb + 4];
                uint32_t bL0 = KL[nb], bL1 = KL[nb + 4];
                mma_bf16(sacc[j], qH[s][0], qH[s][1], qH[s][2], qH[s][3], bH0, bH1);
                mma_bf16(sacc[j], qH[s][0], qH[s][1], qH[s][2], qH[s][3], bL0, bL1);
                mma_bf16(sacc[j], qL[s][0], qL[s][1], qL[s][2], qL[s][3], bH0, bH1);
            }
        }
        // scale + causal mask (diagonal tile only)
        #pragma unroll
        for (int j = 0; j < 8; j++)
            #pragma unroll
            for (int c = 0; c < 4; c++) sacc[j][c] *= scale;
        if (kb == qt) {
            #pragma unroll
            for (int j = 0; j < 8; j++) {
                int c0 = 8 * j + 2 * t4;
                if (c0 > rA)     sacc[j][0] = -1e30f;
                if (c0 + 1 > rA) sacc[j][1] = -1e30f;
                if (c0 > rB)     sacc[j][2] = -1e30f;
                if (c0 + 1 > rB) sacc[j][3] = -1e30f;
            }
        }

        // ---- online softmax over the two rows this thread covers ----
        float mxA = -1e30f, mxB = -1e30f;
        #pragma unroll
        for (int j = 0; j < 8; j++) {
            mxA = fmaxf(mxA, fmaxf(sacc[j][0], sacc[j][1]));
            mxB = fmaxf(mxB, fmaxf(sacc[j][2], sacc[j][3]));
        }
        mxA = fmaxf(mxA, __shfl_xor_sync(0xffffffffu, mxA, 1));
        mxA = fmaxf(mxA, __shfl_xor_sync(0xffffffffu, mxA, 2));
        mxB = fmaxf(mxB, __shfl_xor_sync(0xffffffffu, mxB, 1));
        mxB = fmaxf(mxB, __shfl_xor_sync(0xffffffffu, mxB, 2));
        float nmA = fmaxf(mA, mxA), nmB = fmaxf(mB, mxB);
        float aA = __expf(mA - nmA), aB = __expf(mB - nmB);
        mA = nmA; mB = nmB;
        float sumA = 0.f, sumB = 0.f;
        #pragma unroll
        for (int j = 0; j < 8; j++) {
            float p0 = __expf(sacc[j][0] - nmA);
            float p1 = __expf(sacc[j][1] - nmA);
            float p2 = __expf(sacc[j][2] - nmB);
            float p3 = __expf(sacc[j][3] - nmB);
            sumA += p0 + p1; sumB += p2 + p3;
            uint32_t hh, ll;
            split_pack(p0, p1, hh, ll);
            PH[rA * SAT + 4 * j + t4] = hh; PL[rA * SAT + 4 * j + t4] = ll;
            split_pack(p2, p3, hh, ll);
            PH[rB * SAT + 4 * j + t4] = hh; PL[rB * SAT + 4 * j + t4] = ll;
        }
        sumA += __shfl_xor_sync(0xffffffffu, sumA, 1);
        sumA += __shfl_xor_sync(0xffffffffu, sumA, 2);
        sumB += __shfl_xor_sync(0xffffffffu, sumB, 1);
        sumB += __shfl_xor_sync(0xffffffffu, sumB, 2);
        lA = lA * aA + sumA;
        lB = lB * aB + sumB;
        #pragma unroll
        for (int j = 0; j < 8; j++) {
            oacc[j][0] *= aA; oacc[j][1] *= aA;
            oacc[j][2] *= aB; oacc[j][3] *= aB;
        }
        __syncwarp();   // P rows are per-warp private; order STS before LDS

        // ---- O += P @ V ----
        #pragma unroll
        for (int s = 0; s < 4; s++) {
            int pa = rA * SAT + 8 * s + t4, pb = rB * SAT + 8 * s + t4;
            uint32_t aH0 = PH[pa], aH1 = PH[pb], aH2 = PH[pa + 4], aH3 = PH[pb + 4];
            uint32_t aL0 = PL[pa], aL1 = PL[pb], aL2 = PL[pa + 4], aL3 = PL[pb + 4];
            #pragma unroll
            for (int j = 0; j < 8; j++) {
                int nb = (8 * j + tg) * SAT + 8 * s + t4;
                uint32_t bH0 = VH[nb], bH1 = VH[nb + 4];
                uint32_t bL0 = VL[nb], bL1 = VL[nb + 4];
                mma_bf16(oacc[j], aH0, aH1, aH2, aH3, bH0, bH1);
                mma_bf16(oacc[j], aH0, aH1, aH2, aH3, bL0, bL1);
                mma_bf16(oacc[j], aL0, aL1, aL2, aL3, bH0, bH1);
            }
        }
        __syncthreads();   // protect K/V/P smem before next tile's staging
    }

    // ---- write O (normalized) ----
    float ilA = 1.f / lA, ilB = 1.f / lB;
    float* Ag = g_A + (size_t)(b * SEQ + qt * 64) * DIM + h * HD;
    #pragma unroll
    for (int j = 0; j < 8; j++) {
        int col = 8 * j + 2 * t4;
        *(float2*)(Ag + (size_t)rA * DIM + col) =
            make_float2(oacc[j][0] * ilA, oacc[j][1] * ilA);
        *(float2*)(Ag + (size_t)rB * DIM + col) =
            make_float2(oacc[j][2] * ilB, oacc[j][3] * ilB);
    }
}

// ---------------- launch ----------------------------------------------------
extern "C" void kernel_launch(void* const* d_in, const int* in_sizes, int n_in,
                              void* d_out, int out_size) {
    const float* x  = (const float*)d_in[0];
    const float* fc = (const float*)d_in[1];
    const float* fs = (const float*)d_in[2];
    const float* wq = (const float*)d_in[3];
    const float* wk = (const float*)d_in[4];
    const float* wv = (const float*)d_in[5];
    const float* wo = (const float*)d_in[6];
    float* out = (float*)d_out;

    void *pQ, *pK, *pV, *pA;
    cudaGetSymbolAddress(&pQ, g_Q);
    cudaGetSymbolAddress(&pK, g_K);
    cudaGetSymbolAddress(&pV, g_V);
    cudaGetSymbolAddress(&pA, g_A);
    float* Q = (float*)pQ;
    float* K = (float*)pK;
    float* V = (float*)pV;
    float* A = (float*)pA;

    // projections (tensor-core split-bf16)
    gemm_split<<<dim3(DIM / 128, ROWS / 128), 256>>>(x, wq, Q, ROWS, DIM, DIM);
    gemm_split<<<dim3(KVDIM / 128, ROWS / 128), 256>>>(x, wk, K, ROWS, KVDIM, DIM);
    gemm_split<<<dim3(KVDIM / 128, ROWS / 128), 256>>>(x, wv, V, ROWS, KVDIM, DIM);

    // RoPE
    {
        int totq = ROWS * N_HEADS * 32;
        rope_kernel<<<(totq + 255) / 256, 256>>>(Q, fc, fs, N_HEADS, totq);
        int totk = ROWS * N_KVH * 32;
        rope_kernel<<<(totk + 255) / 256, 256>>>(K, fc, fs, N_KVH, totk);
    }

    // attention (tensor-core split-bf16 flash)
    {
        size_t smem = 6 * 64 * SAT * sizeof(uint32_t);  // 55296 B
        cudaFuncSetAttribute(attn_mma,
                             cudaFuncAttributeMaxDynamicSharedMemorySize,
                             (int)smem);
        attn_mma<<<dim3(SEQ / 64, N_HEADS, BSZ), 128, smem>>>();
    }

    // output projection
    gemm_split<<<dim3(DIM / 128, ROWS / 128), 256>>>(A, wo, out, ROWS, DIM, DIM);
}

// round 3
// speedup vs baseline: 4.7614x; 1.3552x over previous
#include <cuda_runtime.h>
#include <cuda_bf16.h>
#include <cstdint>

#define BSZ      2
#define SEQ      2048
#define DIM      2048
#define N_HEADS  32
#define N_KVH    8
#define HD       64
#define ROWS     (BSZ*SEQ)          // 4096
#define KVDIM    (N_KVH*HD)         // 512
#define KP       (DIM/2)            // 1024 u32 pairs per DIM row
#define KVP      (KVDIM/2)          // 256

// ---------------- scratch (device globals; no allocations allowed) ----------
__device__ __align__(256) float    g_Q[ROWS * DIM];       // fp32 pre-rope Q
__device__ __align__(256) float    g_K[ROWS * KVDIM];
__device__ __align__(256) float    g_V[ROWS * KVDIM];
// split-bf16 (stored as u32 = packed bf16x2 along k)
__device__ __align__(256) uint32_t g_xh [ROWS * KP],   g_xl [ROWS * KP];
__device__ __align__(256) uint32_t g_wqTh[DIM * KP],   g_wqTl[DIM * KP];
__device__ __align__(256) uint32_t g_wkTh[KVDIM * KP], g_wkTl[KVDIM * KP];
__device__ __align__(256) uint32_t g_wvTh[KVDIM * KP], g_wvTl[KVDIM * KP];
__device__ __align__(256) uint32_t g_woTh[DIM * KP],   g_woTl[DIM * KP];
__device__ __align__(256) uint32_t g_Qh[ROWS * KP],    g_Ql[ROWS * KP];
__device__ __align__(256) uint32_t g_Kh[ROWS * KVP],   g_Kl[ROWS * KVP];
__device__ __align__(256) uint32_t g_Vth[BSZ*N_KVH*HD*(SEQ/2)], g_Vtl[BSZ*N_KVH*HD*(SEQ/2)];
__device__ __align__(256) uint32_t g_Ah[ROWS * KP],    g_Al[ROWS * KP];

// ---------------- helpers ----------------------------------------------------
__device__ __forceinline__ void split_pack(float x, float y, uint32_t& hv, uint32_t& lv) {
    __nv_bfloat162 hb = __floats2bfloat162_rn(x, y);
    hv = *reinterpret_cast<uint32_t*>(&hb);
    float rx = x - __bfloat162float(hb.x);
    float ry = y - __bfloat162float(hb.y);
    __nv_bfloat162 lb = __floats2bfloat162_rn(rx, ry);
    lv = *reinterpret_cast<uint32_t*>(&lb);
}

__device__ __forceinline__ void mma_bf16(float* c,
        uint32_t a0, uint32_t a1, uint32_t a2, uint32_t a3,
        uint32_t b0, uint32_t b1) {
    asm volatile(
        "mma.sync.aligned.m16n8k16.row.col.f32.bf16.bf16.f32 "
        "{%0,%1,%2,%3}, {%4,%5,%6,%7}, {%8,%9}, {%0,%1,%2,%3};"
        : "+f"(c[0]), "+f"(c[1]), "+f"(c[2]), "+f"(c[3])
        : "r"(a0), "r"(a1), "r"(a2), "r"(a3), "r"(b0), "r"(b1));
}

__device__ __forceinline__ void cpa16(uint32_t dst_smem, const void* src) {
    asm volatile("cp.async.cg.shared.global [%0], [%1], 16;\n"
                 :: "r"(dst_smem), "l"(src));
}
#define CP_COMMIT asm volatile("cp.async.commit_group;\n" ::)
#define CP_WAIT0  asm volatile("cp.async.wait_group 0;\n" ::)
#define CP_WAIT1  asm volatile("cp.async.wait_group 1;\n" ::)

// ---------------- conversion kernels ----------------------------------------
// x (fp32 [M][K]) -> split bf16 pairs
__global__ void conv_x(const float* __restrict__ x,
                       uint32_t* __restrict__ xh, uint32_t* __restrict__ xl,
                       int npairs) {
    int i = blockIdx.x * blockDim.x + threadIdx.x;
    if (i >= npairs) return;
    float2 v = *(const float2*)(x + 2 * (size_t)i);
    uint32_t h, l;
    split_pack(v.x, v.y, h, l);
    xh[i] = h; xl[i] = l;
}

// W (fp32 [K][N]) -> WT split bf16 pairs [N][K/2]
__global__ __launch_bounds__(256) void tconv(const float* __restrict__ W,
                                             uint32_t* __restrict__ Th,
                                             uint32_t* __restrict__ Tl,
                                             int K, int N) {
    __shared__ float s[64][33];
    const int tid = threadIdx.x;
    const int n0 = blockIdx.x * 32, k0 = blockIdx.y * 64;
    #pragma unroll
    for (int jj = 0; jj < 8; jj++) {
        int id = tid + 256 * jj;
        int k = id >> 5, n = id & 31;
        s[k][n] = W[(size_t)(k0 + k) * N + n0 + n];
    }
    __syncthreads();
    #pragma unroll
    for (int jj = 0; jj < 4; jj++) {
        int id = tid + 256 * jj;
        int n = id >> 5, kp = id & 31;
        uint32_t h, l;
        split_pack(s[2 * kp][n], s[2 * kp + 1][n], h, l);
        size_t o = (size_t)(n0 + n) * (K / 2) + (k0 >> 1) + kp;
        Th[o] = h; Tl[o] = l;
    }
}

// rope + split (Q or K)
__global__ void rope_conv(const float* __restrict__ t,
                          uint32_t* __restrict__ th, uint32_t* __restrict__ tl,
                          const float* __restrict__ cs, const float* __restrict__ sn,
                          int n_heads, int total) {
    int idx = blockIdx.x * blockDim.x + threadIdx.x;
    if (idx >= total) return;
    int p = idx & 31;
    int h = (idx >> 5) % n_heads;
    int row = idx / (32 * n_heads);
    int s = row & (SEQ - 1);
    float c = cs[s * 32 + p];
    float si = sn[s * 32 + p];
    size_t base = (size_t)row * (n_heads * HD) + h * HD + 2 * p;
    float tr = t[base], ti = t[base + 1];
    float orr = tr * c - ti * si;
    float oi  = tr * si + ti * c;
    uint32_t hh, ll;
    split_pack(orr, oi, hh, ll);
    size_t o = (size_t)row * (n_heads * 32) + h * 32 + p;
    th[o] = hh; tl[o] = ll;
}

// V (fp32 [b][s][kvh*64+d]) -> Vt split bf16 [b*8+kvh][d][s/2 pairs]
__global__ __launch_bounds__(256) void vt_conv(const float* __restrict__ V,
                                               uint32_t* __restrict__ Vth,
                                               uint32_t* __restrict__ Vtl) {
    __shared__ float s[32][65];
    const int tid = threadIdx.x;
    const int s0 = blockIdx.x * 32;       // seq block
    const int bz = blockIdx.z;            // b*8+kvh
    const int b = bz >> 3, kvh = bz & 7;
    #pragma unroll
    for (int jj = 0; jj < 8; jj++) {
        int id = tid + 256 * jj;
        int si = id >> 6, d = id & 63;
        s[si][d] = V[(size_t)(b * SEQ + s0 + si) * KVDIM + kvh * HD + d];
    }
    __syncthreads();
    #pragma unroll
    for (int jj = 0; jj < 4; jj++) {
        int id = tid + 256 * jj;
        int d = id >> 4, sp = id & 15;
        uint32_t h, l;
        split_pack(s[2 * sp][d], s[2 * sp + 1][d], h, l);
        size_t o = (size_t)(bz * HD + d) * (SEQ / 2) + (s0 >> 1) + sp;
        Vth[o] = h; Vtl[o] = l;
    }
}

// ---------------- pipelined split-bf16 GEMM ---------------------------------
// C[M,N] = A[M,K] @ B[K,N]; A given as split pairs [M][K/2]; B given transposed
// split pairs [N][K/2]. 128x128 tile, BK=32, 256 threads, double-buffered cp.async.
#define SG   20                     // padded u32 row stride in smem
#define TBUF (4 * 128 * SG)         // u32 per buffer (AH,AL,BH,BL)

__global__ __launch_bounds__(256) void gemm_bf16(
        const uint32_t* __restrict__ Ah, const uint32_t* __restrict__ Al,
        const uint32_t* __restrict__ Bh, const uint32_t* __restrict__ Bl,
        float* __restrict__ C, int M, int N, int K) {
    extern __shared__ uint32_t sm[];
    const int KPL = K >> 1;
    const int tid = threadIdx.x;
    const int warp = tid >> 5, lane = tid & 31;
    const int tg = lane >> 2, t4 = lane & 3;
    const int wm = (warp >> 2) * 64;
    const int wn = (warp & 3) * 32;
    const int bx = blockIdx.x, by = blockIdx.y;

    // per-thread cp.async slots: 8 x 16B
    const uint32_t* src[8];
    uint32_t dstoff[8];   // u32 offset within buffer
    #pragma unroll
    for (int jj = 0; jj < 8; jj++) {
        int id = tid + 256 * jj;
        int arr = id >> 9, rem = id & 511;
        int row = rem >> 2, ch = rem & 3;
        const uint32_t* base =
            (arr == 0) ? Ah + (size_t)(by * 128 + row) * KPL :
            (arr == 1) ? Al + (size_t)(by * 128 + row) * KPL :
            (arr == 2) ? Bh + (size_t)(bx * 128 + row) * KPL :
                         Bl + (size_t)(bx * 128 + row) * KPL;
        src[jj] = base + ch * 4;
        dstoff[jj] = arr * (128 * SG) + row * SG + ch * 4;
    }
    uint32_t sbase = (uint32_t)__cvta_generic_to_shared(sm);

    float acc[4][4][4];
    #pragma unroll
    for (int i = 0; i < 4; i++)
        #pragma unroll
        for (int j = 0; j < 4; j++)
            #pragma unroll
            for (int c = 0; c < 4; c++) acc[i][j][c] = 0.f;

    const int nk = K >> 5;   // chunks of 32

    // prologue: stage chunk 0 into buf 0
    #pragma unroll
    for (int jj = 0; jj < 8; jj++)
        cpa16(sbase + dstoff[jj] * 4, src[jj]);
    CP_COMMIT;

    for (int kc = 0; kc < nk; kc++) {
        int cur = kc & 1;
        if (kc + 1 < nk) {
            uint32_t boff = sbase + (cur ^ 1) * (TBUF * 4);
            int kadv = (kc + 1) * 16;   // u32 advance
            #pragma unroll
            for (int jj = 0; jj < 8; jj++)
                cpa16(boff + dstoff[jj] * 4, src[jj] + kadv);
            CP_COMMIT;
            CP_WAIT1;
        } else {
            CP_WAIT0;
        }
        __syncthreads();

        uint32_t* AH = sm + cur * TBUF;
        uint32_t* AL = AH + 128 * SG;
        uint32_t* BH = AL + 128 * SG;
        uint32_t* BL = BH + 128 * SG;

        #pragma unroll
        for (int s = 0; s < 2; s++) {
            uint32_t aH[4][4], aL[4][4];
            #pragma unroll
            for (int i = 0; i < 4; i++) {
                int ba = (wm + 16 * i + tg) * SG + 8 * s + t4;
                int bb = (wm + 16 * i + 8 + tg) * SG + 8 * s + t4;
                aH[i][0] = AH[ba]; aH[i][1] = AH[bb];
                aH[i][2] = AH[ba + 4]; aH[i][3] = AH[bb + 4];
                aL[i][0] = AL[ba]; aL[i][1] = AL[bb];
                aL[i][2] = AL[ba + 4]; aL[i][3] = AL[bb + 4];
            }
            #pragma unroll
            for (int j = 0; j < 4; j++) {
                int nb = (wn + 8 * j + tg) * SG + 8 * s + t4;
                uint32_t bH0 = BH[nb], bH1 = BH[nb + 4];
                uint32_t bL0 = BL[nb], bL1 = BL[nb + 4];
                #pragma unroll
                for (int i = 0; i < 4; i++) {
                    mma_bf16(acc[i][j], aH[i][0], aH[i][1], aH[i][2], aH[i][3], bH0, bH1);
                    mma_bf16(acc[i][j], aH[i][0], aH[i][1], aH[i][2], aH[i][3], bL0, bL1);
                    mma_bf16(acc[i][j], aL[i][0], aL[i][1], aL[i][2], aL[i][3], bH0, bH1);
                }
            }
        }
        __syncthreads();
    }

    #pragma unroll
    for (int i = 0; i < 4; i++) {
        int r0 = by * 128 + wm + 16 * i + tg;
        #pragma unroll
        for (int j = 0; j < 4; j++) {
            int col = bx * 128 + wn + 8 * j + 2 * t4;
            *(float2*)(C + (size_t)r0 * N + col) = make_float2(acc[i][j][0], acc[i][j][1]);
            *(float2*)(C + (size_t)(r0 + 8) * N + col) = make_float2(acc[i][j][2], acc[i][j][3]);
        }
    }
}

// ---------------- causal flash attention (pipelined split-bf16 mma) ---------
// CTA: 128 q-rows x one (b,h); 8 warps x 16 rows; KV tile 64, double-buffered.
#define SAT   36
#define KVBUF (4 * 64 * SAT)   // u32 per buffer (KH,KL,VH,VL)

__global__ __launch_bounds__(256) void attn_mma() {
    extern __shared__ uint32_t smu[];
    uint32_t* PH = smu + 2 * KVBUF;        // [128][SAT]
    uint32_t* PL = PH + 128 * SAT;

    const int qt = blockIdx.x, h = blockIdx.y, b = blockIdx.z;
    const int kvh = h >> 2;
    const int tid = threadIdx.x;
    const int w = tid >> 5, lane = tid & 31;
    const int tg = lane >> 2, t4 = lane & 3;
    const int rA = w * 16 + tg, rB = rA + 8;
    const int rowAg = b * SEQ + qt * 128 + rA;
    const int rowBg = rowAg + 8;

    // cp.async slots
    const uint32_t* src[8];
    int step[8];
    uint32_t dstoff[8];
    #pragma unroll
    for (int jj = 0; jj < 8; jj++) {
        int id = tid + 256 * jj;
        int arr = id >> 9, rem = id & 511;
        int row = rem >> 3, ch = rem & 7;
        const uint32_t* base;
        if (arr == 0)      base = g_Kh + (size_t)(b * SEQ + row) * KVP + kvh * 32;
        else if (arr == 1) base = g_Kl + (size_t)(b * SEQ + row) * KVP + kvh * 32;
        else if (arr == 2) base = g_Vth + (size_t)((b * 8 + kvh) * HD + row) * (SEQ / 2);
        else               base = g_Vtl + (size_t)((b * 8 + kvh) * HD + row) * (SEQ / 2);
        src[jj] = base + ch * 4;
        step[jj] = (arr < 2) ? 64 * KVP : 32;   // u32 per kv-tile
        dstoff[jj] = arr * (64 * SAT) + row * SAT + ch * 4;
    }
    uint32_t sbase = (uint32_t)__cvta_generic_to_shared(smu);

    // Q fragments straight from global (pre-rope-split)
    uint32_t qH[4][4], qL[4][4];
    {
        const uint32_t* QA = g_Qh + (size_t)rowAg * KP + h * 32;
        const uint32_t* QB = g_Qh + (size_t)rowBg * KP + h * 32;
        const uint32_t* qA = g_Ql + (size_t)rowAg * KP + h * 32;
        const uint32_t* qB = g_Ql + (size_t)rowBg * KP + h * 32;
        #pragma unroll
        for (int s = 0; s < 4; s++) {
            qH[s][0] = QA[8 * s + t4];     qH[s][1] = QB[8 * s + t4];
            qH[s][2] = QA[8 * s + t4 + 4]; qH[s][3] = QB[8 * s + t4 + 4];
            qL[s][0] = qA[8 * s + t4];     qL[s][1] = qB[8 * s + t4];
            qL[s][2] = qA[8 * s + t4 + 4]; qL[s][3] = qB[8 * s + t4 + 4];
        }
    }

    float oacc[8][4];
    #pragma unroll
    for (int j = 0; j < 8; j++)
        #pragma unroll
        for (int c = 0; c < 4; c++) oacc[j][c] = 0.f;
    float mA = -1e30f, mB = -1e30f, lA = 0.f, lB = 0.f;
    const float scale = 0.125f;

    const int nkb = 2 * qt + 2;

    // prologue
    #pragma unroll
    for (int jj = 0; jj < 8; jj++)
        cpa16(sbase + dstoff[jj] * 4, src[jj]);
    CP_COMMIT;

    for (int kb = 0; kb < nkb; kb++) {
        int cur = kb & 1;
        if (kb + 1 < nkb) {
            uint32_t boff = sbase + (cur ^ 1) * (KVBUF * 4);
            #pragma unroll
            for (int jj = 0; jj < 8; jj++)
                cpa16(boff + dstoff[jj] * 4, src[jj] + (size_t)(kb + 1) * step[jj]);
            CP_COMMIT;
            CP_WAIT1;
        } else {
            CP_WAIT0;
        }
        __syncthreads();

        uint32_t* KH = smu + cur * KVBUF;
        uint32_t* KL = KH + 64 * SAT;
        uint32_t* VH = KL + 64 * SAT;
        uint32_t* VL = VH + 64 * SAT;

        // ---- S = Q K^T ----
        float sacc[8][4];
        #pragma unroll
        for (int j = 0; j < 8; j++)
            #pragma unroll
            for (int c = 0; c < 4; c++) sacc[j][c] = 0.f;
        #pragma unroll
        for (int s = 0; s < 4; s++) {
            #pragma unroll
            for (int j = 0; j < 8; j++) {
                int nb = (8 * j + tg) * SAT + 8 * s + t4;
                uint32_t bH0 = KH[nb], bH1 = KH[nb + 4];
                uint32_t bL0 = KL[nb], bL1 = KL[nb + 4];
                mma_bf16(sacc[j], qH[s][0], qH[s][1], qH[s][2], qH[s][3], bH0, bH1);
                mma_bf16(sacc[j], qH[s][0], qH[s][1], qH[s][2], qH[s][3], bL0, bL1);
                mma_bf16(sacc[j], qL[s][0], qL[s][1], qL[s][2], qL[s][3], bH0, bH1);
            }
        }
        #pragma unroll
        for (int j = 0; j < 8; j++)
            #pragma unroll
            for (int c = 0; c < 4; c++) sacc[j][c] *= scale;
        if (kb >= 2 * qt) {   // diagonal region: causal mask
            int rGA = qt * 128 + rA, rGB = rGA + 8;
            #pragma unroll
            for (int j = 0; j < 8; j++) {
                int c0 = kb * 64 + 8 * j + 2 * t4;
                if (c0 > rGA)     sacc[j][0] = -1e30f;
                if (c0 + 1 > rGA) sacc[j][1] = -1e30f;
                if (c0 > rGB)     sacc[j][2] = -1e30f;
                if (c0 + 1 > rGB) sacc[j][3] = -1e30f;
            }
        }

        // ---- online softmax ----
        float mxA = -1e30f, mxB = -1e30f;
        #pragma unroll
        for (int j = 0; j < 8; j++) {
            mxA = fmaxf(mxA, fmaxf(sacc[j][0], sacc[j][1]));
            mxB = fmaxf(mxB, fmaxf(sacc[j][2], sacc[j][3]));
        }
        mxA = fmaxf(mxA, __shfl_xor_sync(0xffffffffu, mxA, 1));
        mxA = fmaxf(mxA, __shfl_xor_sync(0xffffffffu, mxA, 2));
        mxB = fmaxf(mxB, __shfl_xor_sync(0xffffffffu, mxB, 1));
        mxB = fmaxf(mxB, __shfl_xor_sync(0xffffffffu, mxB, 2));
        float nmA = fmaxf(mA, mxA), nmB = fmaxf(mB, mxB);
        float aA = __expf(mA - nmA), aB = __expf(mB - nmB);
        mA = nmA; mB = nmB;
        float sumA = 0.f, sumB = 0.f;
        #pragma unroll
        for (int j = 0; j < 8; j++) {
            float p0 = __expf(sacc[j][0] - nmA);
            float p1 = __expf(sacc[j][1] - nmA);
            float p2 = __expf(sacc[j][2] - nmB);
            float p3 = __expf(sacc[j][3] - nmB);
            sumA += p0 + p1; sumB += p2 + p3;
            uint32_t hh, ll;
            split_pack(p0, p1, hh, ll);
            PH[rA * SAT + 4 * j + t4] = hh; PL[rA * SAT + 4 * j + t4] = ll;
            split_pack(p2, p3, hh, ll);
            PH[rB * SAT + 4 * j + t4] = hh; PL[rB * SAT + 4 * j + t4] = ll;
        }
        sumA += __shfl_xor_sync(0xffffffffu, sumA, 1);
        sumA += __shfl_xor_sync(0xffffffffu, sumA, 2);
        sumB += __shfl_xor_sync(0xffffffffu, sumB, 1);
        sumB += __shfl_xor_sync(0xffffffffu, sumB, 2);
        lA = lA * aA + sumA;
        lB = lB * aB + sumB;
        #pragma unroll
        for (int j = 0; j < 8; j++) {
            oacc[j][0] *= aA; oacc[j][1] *= aA;
            oacc[j][2] *= aB; oacc[j][3] *= aB;
        }
        __syncwarp();   // P rows are per-warp private

        // ---- O += P @ V ----
        #pragma unroll
        for (int s = 0; s < 4; s++) {
            int pa = rA * SAT + 8 * s + t4, pb = rB * SAT + 8 * s + t4;
            uint32_t aH0 = PH[pa], aH1 = PH[pb], aH2 = PH[pa + 4], aH3 = PH[pb + 4];
            uint32_t aL0 = PL[pa], aL1 = PL[pb], aL2 = PL[pa + 4], aL3 = PL[pb + 4];
            #pragma unroll
            for (int j = 0; j < 8; j++) {
                int nb = (8 * j + tg) * SAT + 8 * s + t4;
                uint32_t bH0 = VH[nb], bH1 = VH[nb + 4];
                uint32_t bL0 = VL[nb], bL1 = VL[nb + 4];
                mma_bf16(oacc[j], aH0, aH1, aH2, aH3, bH0, bH1);
                mma_bf16(oacc[j], aH0, aH1, aH2, aH3, bL0, bL1);
                mma_bf16(oacc[j], aL0, aL1, aL2, aL3, bH0, bH1);
            }
        }
        __syncthreads();
    }

    // ---- write O as split bf16 (feeds O-projection) ----
    float ilA = 1.f / lA, ilB = 1.f / lB;
    #pragma unroll
    for (int j = 0; j < 8; j++) {
        uint32_t hh, ll;
        size_t oA = (size_t)rowAg * KP + h * 32 + 4 * j + t4;
        size_t oB = (size_t)rowBg * KP + h * 32 + 4 * j + t4;
        split_pack(oacc[j][0] * ilA, oacc[j][1] * ilA, hh, ll);
        g_Ah[oA] = hh; g_Al[oA] = ll;
        split_pack(oacc[j][2] * ilB, oacc[j][3] * ilB, hh, ll);
        g_Ah[oB] = hh; g_Al[oB] = ll;
    }
}

// ---------------- launch ----------------------------------------------------
extern "C" void kernel_launch(void* const* d_in, const int* in_sizes, int n_in,
                              void* d_out, int out_size) {
    const float* x  = (const float*)d_in[0];
    const float* fc = (const float*)d_in[1];
    const float* fs = (const float*)d_in[2];
    const float* wq = (const float*)d_in[3];
    const float* wk = (const float*)d_in[4];
    const float* wv = (const float*)d_in[5];
    const float* wo = (const float*)d_in[6];
    float* out = (float*)d_out;

    void *pQ, *pK, *pV;
    void *pxh, *pxl, *pwqh, *pwql, *pwkh, *pwkl, *pwvh, *pwvl, *pwoh, *pwol;
    void *pQh, *pQl, *pKh, *pKl, *pVth, *pVtl, *pAh, *pAl;
    cudaGetSymbolAddress(&pQ, g_Q);
    cudaGetSymbolAddress(&pK, g_K);
    cudaGetSymbolAddress(&pV, g_V);
    cudaGetSymbolAddress(&pxh, g_xh);   cudaGetSymbolAddress(&pxl, g_xl);
    cudaGetSymbolAddress(&pwqh, g_wqTh); cudaGetSymbolAddress(&pwql, g_wqTl);
    cudaGetSymbolAddress(&pwkh, g_wkTh); cudaGetSymbolAddress(&pwkl, g_wkTl);
    cudaGetSymbolAddress(&pwvh, g_wvTh); cudaGetSymbolAddress(&pwvl, g_wvTl);
    cudaGetSymbolAddress(&pwoh, g_woTh); cudaGetSymbolAddress(&pwol, g_woTl);
    cudaGetSymbolAddress(&pQh, g_Qh);   cudaGetSymbolAddress(&pQl, g_Ql);
    cudaGetSymbolAddress(&pKh, g_Kh);   cudaGetSymbolAddress(&pKl, g_Kl);
    cudaGetSymbolAddress(&pVth, g_Vth); cudaGetSymbolAddress(&pVtl, g_Vtl);
    cudaGetSymbolAddress(&pAh, g_Ah);   cudaGetSymbolAddress(&pAl, g_Al);

    // ---- one-shot conversions ----
    conv_x<<<(ROWS * KP + 255) / 256, 256>>>(x, (uint32_t*)pxh, (uint32_t*)pxl, ROWS * KP);
    tconv<<<dim3(DIM / 32, DIM / 64), 256>>>(wq, (uint32_t*)pwqh, (uint32_t*)pwql, DIM, DIM);
    tconv<<<dim3(KVDIM / 32, DIM / 64), 256>>>(wk, (uint32_t*)pwkh, (uint32_t*)pwkl, DIM, KVDIM);
    tconv<<<dim3(KVDIM / 32, DIM / 64), 256>>>(wv, (uint32_t*)pwvh, (uint32_t*)pwvl, DIM, KVDIM);
    tconv<<<dim3(DIM / 32, DIM / 64), 256>>>(wo, (uint32_t*)pwoh, (uint32_t*)pwol, DIM, DIM);

    size_t gsmem = 2 * TBUF * sizeof(uint32_t);   // 81920 B
    cudaFuncSetAttribute(gemm_bf16, cudaFuncAttributeMaxDynamicSharedMemorySize, (int)gsmem);

    // ---- projections ----
    gemm_bf16<<<dim3(DIM / 128, ROWS / 128), 256, gsmem>>>(
        (uint32_t*)pxh, (uint32_t*)pxl, (uint32_t*)pwqh, (uint32_t*)pwql,
        (float*)pQ, ROWS, DIM, DIM);
    gemm_bf16<<<dim3(KVDIM / 128, ROWS / 128), 256, gsmem>>>(
        (uint32_t*)pxh, (uint32_t*)pxl, (uint32_t*)pwkh, (uint32_t*)pwkl,
        (float*)pK, ROWS, KVDIM, DIM);
    gemm_bf16<<<dim3(KVDIM / 128, ROWS / 128), 256, gsmem>>>(
        (uint32_t*)pxh, (uint32_t*)pxl, (uint32_t*)pwvh, (uint32_t*)pwvl,
        (float*)pV, ROWS, KVDIM, DIM);

    // ---- rope + split / V transpose-split ----
    {
        int totq = ROWS * N_HEADS * 32;
        rope_conv<<<(totq + 255) / 256, 256>>>((float*)pQ, (uint32_t*)pQh, (uint32_t*)pQl,
                                               fc, fs, N_HEADS, totq);
        int totk = ROWS * N_KVH * 32;
        rope_conv<<<(totk + 255) / 256, 256>>>((float*)pK, (uint32_t*)pKh, (uint32_t*)pKl,
                                               fc, fs, N_KVH, totk);
        vt_conv<<<dim3(SEQ / 32, 1, BSZ * N_KVH), 256>>>((float*)pV,
                                                         (uint32_t*)pVth, (uint32_t*)pVtl);
    }

    // ---- attention ----
    {
        size_t smem = (2 * KVBUF + 2 * 128 * SAT) * sizeof(uint32_t);  // 110592 B
        cudaFuncSetAttribute(attn_mma, cudaFuncAttributeMaxDynamicSharedMemorySize, (int)smem);
        attn_mma<<<dim3(SEQ / 128, N_HEADS, BSZ), 256, smem>>>();
    }

    // ---- output projection ----
    gemm_bf16<<<dim3(DIM / 128, ROWS / 128), 256, gsmem>>>(
        (uint32_t*)pAh, (uint32_t*)pAl, (uint32_t*)pwoh, (uint32_t*)pwol,
        out, ROWS, DIM, DIM);
}